// round 1
// baseline (speedup 1.0000x reference)
#include <cuda_runtime.h>
#include <cuda_bf16.h>
#include <math.h>

// Problem constants
#define NB 64            // B*T = 4*16 sequences
#define S 256
#define D 1024
#define NH 16
#define NKV 4
#define HD 64
#define NIMG 240
#define MROWS (NB * S)   // 16384

// Scratch (static device globals: allocation-free)
__device__ float g_Q[MROWS * D];          // Q projections / post-rope   (64 MB)
__device__ float g_K[MROWS * NKV * HD];   // K projections               (16 MB)
__device__ float g_V[MROWS * NKV * HD];   // V projections               (16 MB)
__device__ float g_O[MROWS * D];          // attention output (pre-Wo)   (64 MB)

// ---------------------------------------------------------------------------
// Tiled SGEMM: C[M,N] = A[M,K] @ B[K,N], all row-major, fp32.
// BM=BN=128, BK=8, 256 threads, 8x8 per-thread microtile.
// Requires M%128==0, N%128==0, K%8==0 (true for all our shapes).
// ---------------------------------------------------------------------------
__global__ void __launch_bounds__(256, 2)
sgemm128(const float* __restrict__ A, const float* __restrict__ B,
         float* __restrict__ C, int M, int N, int K) {
    __shared__ float As[8][128];   // transposed A tile: As[k][m]
    __shared__ float Bs[8][128];

    const int tid = threadIdx.x;
    const int bm = blockIdx.y * 128;
    const int bn = blockIdx.x * 128;

    const int aRow = tid >> 1;            // 0..127
    const int aCol = (tid & 1) * 4;       // 0 or 4
    const int bRow = tid >> 5;            // 0..7
    const int bCol = (tid & 31) * 4;      // 0..124

    const float* Ag = A + (size_t)(bm + aRow) * K + aCol;
    const float* Bg = B + (size_t)bRow * N + bn + bCol;

    const int tx = tid & 15;
    const int ty = tid >> 4;

    float acc[8][8] = {};

    for (int k0 = 0; k0 < K; k0 += 8) {
        float4 a4 = *(const float4*)(Ag + k0);
        float4 b4 = *(const float4*)(Bg + (size_t)k0 * N);
        As[aCol + 0][aRow] = a4.x;
        As[aCol + 1][aRow] = a4.y;
        As[aCol + 2][aRow] = a4.z;
        As[aCol + 3][aRow] = a4.w;
        *(float4*)&Bs[bRow][bCol] = b4;
        __syncthreads();

        #pragma unroll
        for (int k = 0; k < 8; k++) {
            float ra[8], rb[8];
            *(float4*)(ra)     = *(const float4*)&As[k][ty * 8];
            *(float4*)(ra + 4) = *(const float4*)&As[k][ty * 8 + 4];
            *(float4*)(rb)     = *(const float4*)&Bs[k][tx * 8];
            *(float4*)(rb + 4) = *(const float4*)&Bs[k][tx * 8 + 4];
            #pragma unroll
            for (int i = 0; i < 8; i++)
                #pragma unroll
                for (int j = 0; j < 8; j++)
                    acc[i][j] = fmaf(ra[i], rb[j], acc[i][j]);
        }
        __syncthreads();
    }

    #pragma unroll
    for (int i = 0; i < 8; i++) {
        float* Cp = C + (size_t)(bm + ty * 8 + i) * N + bn + tx * 8;
        *(float4*)(Cp)     = make_float4(acc[i][0], acc[i][1], acc[i][2], acc[i][3]);
        *(float4*)(Cp + 4) = make_float4(acc[i][4], acc[i][5], acc[i][6], acc[i][7]);
    }
}

// ---------------------------------------------------------------------------
// RMSNorm + RoPE, in place on g_Q and g_K. One warp per (n,s,head).
// Q warps: 64*256*16 = 262144 ; K warps: 64*256*4 = 65536 ; total 327680.
// ---------------------------------------------------------------------------
__global__ void __launch_bounds__(256)
rmsrope_kernel(const float* __restrict__ rope_cos, const float* __restrict__ rope_sin,
               const float* __restrict__ q_scale, const float* __restrict__ k_scale) {
    const int w = blockIdx.x * 8 + (threadIdx.x >> 5);
    const int lane = threadIdx.x & 31;

    float* p;
    const float* scale;
    int s_idx;
    if (w < 262144) {
        int ns = w >> 4;           // n*256 + s
        int h  = w & 15;
        p = g_Q + (size_t)ns * D + h * HD;
        scale = q_scale;
        s_idx = ns & 255;
    } else {
        int w2 = w - 262144;
        int ns = w2 >> 2;
        int h  = w2 & 3;
        p = g_K + (size_t)ns * (NKV * HD) + h * HD;
        scale = k_scale;
        s_idx = ns & 255;
    }

    float v1 = p[lane];
    float v2 = p[lane + 32];
    float ss = v1 * v1 + v2 * v2;
    #pragma unroll
    for (int o = 16; o; o >>= 1) ss += __shfl_xor_sync(0xffffffffu, ss, o);
    float r = rsqrtf(ss * (1.0f / 64.0f) + 1e-6f);

    float a = v1 * r * scale[lane];
    float b = v2 * r * scale[lane + 32];
    float c  = rope_cos[s_idx * 32 + lane];
    float sn = rope_sin[s_idx * 32 + lane];
    p[lane]      = a * c - b * sn;
    p[lane + 32] = b * c + a * sn;
}

// ---------------------------------------------------------------------------
// Attention: one CTA per (n, h). 256 threads = 8 warps, each warp owns 32 q
// rows processed 4 at a time (register blocked). K/V in smem with 65-float
// row pitch (conflict-free for both phases). tanh logit cap + block mask.
// ---------------------------------------------------------------------------
#define KV_PITCH 65
#define ATTN_SMEM_FLOATS (2 * 256 * KV_PITCH + 8 * 4 * 64 + 8 * 4 * 256)

__global__ void __launch_bounds__(256, 1)
attn_kernel(const float* __restrict__ Q, const float* __restrict__ K,
            const float* __restrict__ V, float* __restrict__ O) {
    extern __shared__ float sm[];
    float* Ks  = sm;                         // [256][65]
    float* Vs  = Ks + 256 * KV_PITCH;        // [256][65]
    float* qsh = Vs + 256 * KV_PITCH;        // [8][4][64]
    float* psh = qsh + 8 * 4 * 64;           // [8][4][256]

    const int b = blockIdx.x;
    const int n = b >> 4;
    const int h = b & 15;
    const int hkv = h >> 2;
    const int tid = threadIdx.x;
    const int w = tid >> 5;
    const int lane = tid & 31;

    const float* Kg = g_K + (size_t)n * S * (NKV * HD) + hkv * HD;
    const float* Vg = g_V + (size_t)n * S * (NKV * HD) + hkv * HD;
    (void)K; (void)V;

    // stage K/V tiles into smem (coalesced global reads, conflict-free stores)
    for (int idx = tid; idx < 256 * 64; idx += 256) {
        int s = idx >> 6;
        int d = idx & 63;
        Ks[s * KV_PITCH + d] = Kg[(size_t)s * (NKV * HD) + d];
        Vs[s * KV_PITCH + d] = Vg[(size_t)s * (NKV * HD) + d];
    }
    __syncthreads();

    const float* Qg = Q + (size_t)n * S * D + h * HD;
    float* Og = O + (size_t)n * S * D + h * HD;
    float* myq = qsh + w * 4 * 64;
    float* myp = psh + w * 4 * 256;

    for (int it = 0; it < 8; it++) {
        const int q0 = w * 32 + it * 4;

        #pragma unroll
        for (int r = 0; r < 4; r++) {
            myq[r * 64 + lane]      = Qg[(size_t)(q0 + r) * D + lane];
            myq[r * 64 + lane + 32] = Qg[(size_t)(q0 + r) * D + lane + 32];
        }
        __syncwarp();

        // scores: lane owns k = lane + 32*j
        float acc[4][8] = {};
        #pragma unroll 4
        for (int d = 0; d < 64; d++) {
            float kv[8];
            #pragma unroll
            for (int j = 0; j < 8; j++)
                kv[j] = Ks[(lane + 32 * j) * KV_PITCH + d];
            #pragma unroll
            for (int r = 0; r < 4; r++) {
                float qd = myq[r * 64 + d];
                #pragma unroll
                for (int j = 0; j < 8; j++)
                    acc[r][j] = fmaf(qd, kv[j], acc[r][j]);
            }
        }

        // softmax (tanh cap + mask) per row
        #pragma unroll
        for (int r = 0; r < 4; r++) {
            const int q = q0 + r;
            float sc[8];
            float m = -1e30f;
            #pragma unroll
            for (int j = 0; j < 8; j++) {
                int k = lane + 32 * j;
                float s = acc[r][j] * 0.125f;        // 1/sqrt(64)
                s = 50.0f * tanhf(s * 0.02f);        // logit cap
                bool ok = (q >= NIMG) || (k < NIMG);
                sc[j] = ok ? s : -1e30f;
                m = fmaxf(m, sc[j]);
            }
            #pragma unroll
            for (int o = 16; o; o >>= 1) m = fmaxf(m, __shfl_xor_sync(0xffffffffu, m, o));
            float sum = 0.0f;
            #pragma unroll
            for (int j = 0; j < 8; j++) {
                float e = (sc[j] < -1e29f) ? 0.0f : __expf(sc[j] - m);
                sc[j] = e;
                sum += e;
            }
            #pragma unroll
            for (int o = 16; o; o >>= 1) sum += __shfl_xor_sync(0xffffffffu, sum, o);
            float inv = 1.0f / sum;
            #pragma unroll
            for (int j = 0; j < 8; j++)
                myp[r * 256 + lane + 32 * j] = sc[j] * inv;
        }
        __syncwarp();

        // PV: lane owns output dims d = lane, lane+32
        float o0[4] = {}, o1[4] = {};
        #pragma unroll 4
        for (int k = 0; k < 256; k++) {
            float v0 = Vs[k * KV_PITCH + lane];
            float v1 = Vs[k * KV_PITCH + lane + 32];
            #pragma unroll
            for (int r = 0; r < 4; r++) {
                float pv = myp[r * 256 + k];
                o0[r] = fmaf(pv, v0, o0[r]);
                o1[r] = fmaf(pv, v1, o1[r]);
            }
        }
        #pragma unroll
        for (int r = 0; r < 4; r++) {
            Og[(size_t)(q0 + r) * D + lane]      = o0[r];
            Og[(size_t)(q0 + r) * D + lane + 32] = o1[r];
        }
        __syncwarp();
    }
}

// ---------------------------------------------------------------------------
extern "C" void kernel_launch(void* const* d_in, const int* in_sizes, int n_in,
                              void* d_out, int out_size) {
    const float* x        = (const float*)d_in[0];
    /* d_in[1] = attn_mask — structure is known analytically (N_IMG=240), unused */
    const float* rope_cos = (const float*)d_in[2];
    const float* rope_sin = (const float*)d_in[3];
    const float* Wq       = (const float*)d_in[4];
    const float* Wk       = (const float*)d_in[5];
    const float* Wv       = (const float*)d_in[6];
    const float* Wo       = (const float*)d_in[7];
    const float* q_scale  = (const float*)d_in[8];
    const float* k_scale  = (const float*)d_in[9];
    float* out = (float*)d_out;

    float *qp, *kp, *vp, *op;
    cudaGetSymbolAddress((void**)&qp, g_Q);
    cudaGetSymbolAddress((void**)&kp, g_K);
    cudaGetSymbolAddress((void**)&vp, g_V);
    cudaGetSymbolAddress((void**)&op, g_O);

    static_assert(ATTN_SMEM_FLOATS * 4 < 227 * 1024, "smem budget");
    cudaFuncSetAttribute(attn_kernel, cudaFuncAttributeMaxDynamicSharedMemorySize,
                         ATTN_SMEM_FLOATS * (int)sizeof(float));

    dim3 thr(256);
    // QKV projections
    sgemm128<<<dim3(D / 128, MROWS / 128), thr>>>(x, Wq, qp, MROWS, D, D);
    sgemm128<<<dim3((NKV * HD) / 128, MROWS / 128), thr>>>(x, Wk, kp, MROWS, NKV * HD, D);
    sgemm128<<<dim3((NKV * HD) / 128, MROWS / 128), thr>>>(x, Wv, vp, MROWS, NKV * HD, D);

    // RMSNorm + RoPE on Q and K (in place)
    rmsrope_kernel<<<(262144 + 65536) / 8, thr>>>(rope_cos, rope_sin, q_scale, k_scale);

    // Attention
    attn_kernel<<<NB * NH, thr, ATTN_SMEM_FLOATS * sizeof(float)>>>(qp, kp, vp, op);

    // Output projection
    sgemm128<<<dim3(D / 128, MROWS / 128), thr>>>(op, Wo, out, MROWS, D, D);
}

// round 3
// speedup vs baseline: 1.6000x; 1.6000x over previous
#include <cuda_runtime.h>
#include <cuda_bf16.h>
#include <math.h>

// Problem constants
#define NB 64            // B*T
#define S 256
#define D 1024
#define NH 16
#define NKV 4
#define HD 64
#define NIMG 240
#define MROWS (NB * S)   // 16384

// Scratch
__device__ float g_Q[MROWS * D];
__device__ float g_K[MROWS * NKV * HD];
__device__ float g_V[MROWS * NKV * HD];
__device__ float g_O[MROWS * D];

__device__ __forceinline__ unsigned pack_bf16(__nv_bfloat16 a, __nv_bfloat16 b) {
    return (unsigned)__bfloat16_as_ushort(a) | ((unsigned)__bfloat16_as_ushort(b) << 16);
}
__device__ __forceinline__ void split_bf16(float x, __nv_bfloat16& h, __nv_bfloat16& l) {
    h = __float2bfloat16_rn(x);
    l = __float2bfloat16_rn(x - __bfloat162float(h));
}

// ===========================================================================
// HMMA bf16x3 GEMM: C[M,N] = A[M,K] @ B[K,N], fp32 in/out.
// CTA 128x128, BK=32, 8 warps (2x4), warp tile 64x32, m16n8k16 mma.sync.
// 3 passes per k-step: Ah*Bh + Ah*Bl + Al*Bh (error-compensated bf16).
// ===========================================================================
#define BM 128
#define BN 128
#define BK 32
#define PITCH 40                     // bf16 elems per smem row (80B: conflict-free)
#define TILE_ELEMS (128 * PITCH)     // one 128-row tile
#define GEMM_SMEM (8 * TILE_ELEMS * 2)   // 8 tiles (2 stages x {Ah,Al,Bh,Bl}) bf16

__global__ void __launch_bounds__(256)
gemm_hmma(const float* __restrict__ A, const float* __restrict__ Bm,
          float* __restrict__ C, int M, int N, int K) {
    extern __shared__ __nv_bfloat16 smb[];
    // layout: [stage][part] A tiles at (s*2+p), B tiles at (4 + s*2+p)
    const int tid = threadIdx.x;
    const int wid = tid >> 5;
    const int lane = tid & 31;
    const int lr = lane >> 2;      // 0..7
    const int lc = lane & 3;       // 0..3

    const int bm = blockIdx.y * BM;
    const int bn = blockIdx.x * BN;
    const int wm = (wid >> 2) * 64;
    const int wn = (wid & 3) * 32;

    // staging index precompute
    const int arow = tid >> 3;            // 0..31
    const int akq  = (tid & 7) * 4;       // 0..28
    const int btn  = tid & 127;           // 0..127
    const int bkh  = (tid >> 7) * 16;     // 0 or 16

    const float* Ag = A + (size_t)(bm + arow) * K + akq;
    const float* Bg = Bm + (size_t)bkh * N + bn + btn;

    float c[4][4][4] = {};

    const int NCH = K / BK;

    // ---- helper lambdas ----
    auto store_stage = [&](int s, const float4 av[4], const float bv[16]) {
        __nv_bfloat16* Ah = smb + (s * 2 + 0) * TILE_ELEMS;
        __nv_bfloat16* Al = smb + (s * 2 + 1) * TILE_ELEMS;
        __nv_bfloat16* Bh = smb + (4 + s * 2 + 0) * TILE_ELEMS;
        __nv_bfloat16* Bl = smb + (4 + s * 2 + 1) * TILE_ELEMS;
        #pragma unroll
        for (int i = 0; i < 4; i++) {
            __nv_bfloat16 h0, l0, h1, l1, h2, l2, h3, l3;
            split_bf16(av[i].x, h0, l0);
            split_bf16(av[i].y, h1, l1);
            split_bf16(av[i].z, h2, l2);
            split_bf16(av[i].w, h3, l3);
            int r = arow + i * 32;
            *(uint2*)&Ah[r * PITCH + akq] = make_uint2(pack_bf16(h0, h1), pack_bf16(h2, h3));
            *(uint2*)&Al[r * PITCH + akq] = make_uint2(pack_bf16(l0, l1), pack_bf16(l2, l3));
        }
        #pragma unroll
        for (int j = 0; j < 8; j++) {
            __nv_bfloat16 h0, l0, h1, l1;
            split_bf16(bv[2 * j], h0, l0);
            split_bf16(bv[2 * j + 1], h1, l1);
            *(unsigned*)&Bh[btn * PITCH + bkh + 2 * j] = pack_bf16(h0, h1);
            *(unsigned*)&Bl[btn * PITCH + bkh + 2 * j] = pack_bf16(l0, l1);
        }
    };

    auto compute_stage = [&](int s) {
        #pragma unroll
        for (int ks = 0; ks < 2; ks++) {
            #pragma unroll
            for (int pass = 0; pass < 3; pass++) {
                const __nv_bfloat16* Ap = smb + (s * 2 + (pass == 2 ? 1 : 0)) * TILE_ELEMS;
                const __nv_bfloat16* Bp = smb + (4 + s * 2 + (pass == 1 ? 1 : 0)) * TILE_ELEMS;
                unsigned a[4][4], b[4][2];
                #pragma unroll
                for (int mi = 0; mi < 4; mi++) {
                    int r0 = wm + mi * 16 + lr;
                    int kk = ks * 16 + lc * 2;
                    a[mi][0] = *(const unsigned*)&Ap[r0 * PITCH + kk];
                    a[mi][1] = *(const unsigned*)&Ap[(r0 + 8) * PITCH + kk];
                    a[mi][2] = *(const unsigned*)&Ap[r0 * PITCH + kk + 8];
                    a[mi][3] = *(const unsigned*)&Ap[(r0 + 8) * PITCH + kk + 8];
                }
                #pragma unroll
                for (int ni = 0; ni < 4; ni++) {
                    int n0 = wn + ni * 8 + lr;
                    int kk = ks * 16 + lc * 2;
                    b[ni][0] = *(const unsigned*)&Bp[n0 * PITCH + kk];
                    b[ni][1] = *(const unsigned*)&Bp[n0 * PITCH + kk + 8];
                }
                #pragma unroll
                for (int mi = 0; mi < 4; mi++)
                    #pragma unroll
                    for (int ni = 0; ni < 4; ni++) {
                        asm volatile(
                            "mma.sync.aligned.m16n8k16.row.col.f32.bf16.bf16.f32 "
                            "{%0,%1,%2,%3}, {%4,%5,%6,%7}, {%8,%9}, {%0,%1,%2,%3};"
                            : "+f"(c[mi][ni][0]), "+f"(c[mi][ni][1]),
                              "+f"(c[mi][ni][2]), "+f"(c[mi][ni][3])
                            : "r"(a[mi][0]), "r"(a[mi][1]), "r"(a[mi][2]), "r"(a[mi][3]),
                              "r"(b[ni][0]), "r"(b[ni][1]));
                    }
            }
        }
    };

    // ---- prologue: stage chunk 0 directly ----
    {
        float4 av[4];
        float bv[16];
        #pragma unroll
        for (int i = 0; i < 4; i++) av[i] = *(const float4*)(Ag + (size_t)(i * 32) * K);
        #pragma unroll
        for (int j = 0; j < 16; j++) bv[j] = Bg[(size_t)j * N];
        store_stage(0, av, bv);
    }
    __syncthreads();

    // ---- main loop with register prefetch ----
    for (int ch = 0; ch < NCH; ch++) {
        const int s = ch & 1;
        float4 av[4];
        float bv[16];
        const bool pf = (ch + 1 < NCH);
        if (pf) {
            const int k0n = (ch + 1) * BK;
            #pragma unroll
            for (int i = 0; i < 4; i++)
                av[i] = *(const float4*)(Ag + (size_t)(i * 32) * K + k0n);
            #pragma unroll
            for (int j = 0; j < 16; j++)
                bv[j] = Bg[(size_t)(k0n + j) * N];
        }
        compute_stage(s);
        if (pf) store_stage(s ^ 1, av, bv);
        __syncthreads();
    }

    // ---- epilogue ----
    #pragma unroll
    for (int mi = 0; mi < 4; mi++) {
        #pragma unroll
        for (int ni = 0; ni < 4; ni++) {
            int r = bm + wm + mi * 16 + lr;
            int col = bn + wn + ni * 8 + lc * 2;
            *(float2*)&C[(size_t)r * N + col] =
                make_float2(c[mi][ni][0], c[mi][ni][1]);
            *(float2*)&C[(size_t)(r + 8) * N + col] =
                make_float2(c[mi][ni][2], c[mi][ni][3]);
        }
    }
}

// ===========================================================================
// RMSNorm + RoPE (unchanged, known-good)
// ===========================================================================
__global__ void __launch_bounds__(256)
rmsrope_kernel(const float* __restrict__ rope_cos, const float* __restrict__ rope_sin,
               const float* __restrict__ q_scale, const float* __restrict__ k_scale) {
    const int w = blockIdx.x * 8 + (threadIdx.x >> 5);
    const int lane = threadIdx.x & 31;

    float* p;
    const float* scale;
    int s_idx;
    if (w < 262144) {
        int ns = w >> 4;
        int h  = w & 15;
        p = g_Q + (size_t)ns * D + h * HD;
        scale = q_scale;
        s_idx = ns & 255;
    } else {
        int w2 = w - 262144;
        int ns = w2 >> 2;
        int h  = w2 & 3;
        p = g_K + (size_t)ns * (NKV * HD) + h * HD;
        scale = k_scale;
        s_idx = ns & 255;
    }

    float v1 = p[lane];
    float v2 = p[lane + 32];
    float ss = v1 * v1 + v2 * v2;
    #pragma unroll
    for (int o = 16; o; o >>= 1) ss += __shfl_xor_sync(0xffffffffu, ss, o);
    float r = rsqrtf(ss * (1.0f / 64.0f) + 1e-6f);

    float a = v1 * r * scale[lane];
    float b = v2 * r * scale[lane + 32];
    float c  = rope_cos[s_idx * 32 + lane];
    float sn = rope_sin[s_idx * 32 + lane];
    p[lane]      = a * c - b * sn;
    p[lane + 32] = b * c + a * sn;
}

// ===========================================================================
// Attention (unchanged, known-good fp32)
// ===========================================================================
#define KV_PITCH 65
#define ATTN_SMEM_FLOATS (2 * 256 * KV_PITCH + 8 * 4 * 64 + 8 * 4 * 256)

__global__ void __launch_bounds__(256, 1)
attn_kernel(const float* __restrict__ Q, const float* __restrict__ K,
            const float* __restrict__ V, float* __restrict__ O) {
    extern __shared__ float sm[];
    float* Ks  = sm;
    float* Vs  = Ks + 256 * KV_PITCH;
    float* qsh = Vs + 256 * KV_PITCH;
    float* psh = qsh + 8 * 4 * 64;

    const int b = blockIdx.x;
    const int n = b >> 4;
    const int h = b & 15;
    const int hkv = h >> 2;
    const int tid = threadIdx.x;
    const int w = tid >> 5;
    const int lane = tid & 31;

    const float* Kg = g_K + (size_t)n * S * (NKV * HD) + hkv * HD;
    const float* Vg = g_V + (size_t)n * S * (NKV * HD) + hkv * HD;
    (void)K; (void)V;

    for (int idx = tid; idx < 256 * 64; idx += 256) {
        int s = idx >> 6;
        int d = idx & 63;
        Ks[s * KV_PITCH + d] = Kg[(size_t)s * (NKV * HD) + d];
        Vs[s * KV_PITCH + d] = Vg[(size_t)s * (NKV * HD) + d];
    }
    __syncthreads();

    const float* Qg = Q + (size_t)n * S * D + h * HD;
    float* Og = O + (size_t)n * S * D + h * HD;
    float* myq = qsh + w * 4 * 64;
    float* myp = psh + w * 4 * 256;

    for (int it = 0; it < 8; it++) {
        const int q0 = w * 32 + it * 4;

        #pragma unroll
        for (int r = 0; r < 4; r++) {
            myq[r * 64 + lane]      = Qg[(size_t)(q0 + r) * D + lane];
            myq[r * 64 + lane + 32] = Qg[(size_t)(q0 + r) * D + lane + 32];
        }
        __syncwarp();

        float acc[4][8] = {};
        #pragma unroll 4
        for (int d = 0; d < 64; d++) {
            float kv[8];
            #pragma unroll
            for (int j = 0; j < 8; j++)
                kv[j] = Ks[(lane + 32 * j) * KV_PITCH + d];
            #pragma unroll
            for (int r = 0; r < 4; r++) {
                float qd = myq[r * 64 + d];
                #pragma unroll
                for (int j = 0; j < 8; j++)
                    acc[r][j] = fmaf(qd, kv[j], acc[r][j]);
            }
        }

        #pragma unroll
        for (int r = 0; r < 4; r++) {
            const int q = q0 + r;
            float sc[8];
            float m = -1e30f;
            #pragma unroll
            for (int j = 0; j < 8; j++) {
                int k = lane + 32 * j;
                float s = acc[r][j] * 0.125f;
                s = 50.0f * tanhf(s * 0.02f);
                bool ok = (q >= NIMG) || (k < NIMG);
                sc[j] = ok ? s : -1e30f;
                m = fmaxf(m, sc[j]);
            }
            #pragma unroll
            for (int o = 16; o; o >>= 1) m = fmaxf(m, __shfl_xor_sync(0xffffffffu, m, o));
            float sum = 0.0f;
            #pragma unroll
            for (int j = 0; j < 8; j++) {
                float e = (sc[j] < -1e29f) ? 0.0f : __expf(sc[j] - m);
                sc[j] = e;
                sum += e;
            }
            #pragma unroll
            for (int o = 16; o; o >>= 1) sum += __shfl_xor_sync(0xffffffffu, sum, o);
            float inv = 1.0f / sum;
            #pragma unroll
            for (int j = 0; j < 8; j++)
                myp[r * 256 + lane + 32 * j] = sc[j] * inv;
        }
        __syncwarp();

        float o0[4] = {}, o1[4] = {};
        #pragma unroll 4
        for (int k = 0; k < 256; k++) {
            float v0 = Vs[k * KV_PITCH + lane];
            float v1 = Vs[k * KV_PITCH + lane + 32];
            #pragma unroll
            for (int r = 0; r < 4; r++) {
                float pv = myp[r * 256 + k];
                o0[r] = fmaf(pv, v0, o0[r]);
                o1[r] = fmaf(pv, v1, o1[r]);
            }
        }
        #pragma unroll
        for (int r = 0; r < 4; r++) {
            Og[(size_t)(q0 + r) * D + lane]      = o0[r];
            Og[(size_t)(q0 + r) * D + lane + 32] = o1[r];
        }
        __syncwarp();
    }
}

// ===========================================================================
extern "C" void kernel_launch(void* const* d_in, const int* in_sizes, int n_in,
                              void* d_out, int out_size) {
    const float* x        = (const float*)d_in[0];
    const float* rope_cos = (const float*)d_in[2];
    const float* rope_sin = (const float*)d_in[3];
    const float* Wq       = (const float*)d_in[4];
    const float* Wk       = (const float*)d_in[5];
    const float* Wv       = (const float*)d_in[6];
    const float* Wo       = (const float*)d_in[7];
    const float* q_scale  = (const float*)d_in[8];
    const float* k_scale  = (const float*)d_in[9];
    float* out = (float*)d_out;

    float *qp, *kp, *vp, *op;
    cudaGetSymbolAddress((void**)&qp, g_Q);
    cudaGetSymbolAddress((void**)&kp, g_K);
    cudaGetSymbolAddress((void**)&vp, g_V);
    cudaGetSymbolAddress((void**)&op, g_O);

    cudaFuncSetAttribute(gemm_hmma, cudaFuncAttributeMaxDynamicSharedMemorySize, GEMM_SMEM);
    cudaFuncSetAttribute(attn_kernel, cudaFuncAttributeMaxDynamicSharedMemorySize,
                         ATTN_SMEM_FLOATS * (int)sizeof(float));

    dim3 thr(256);
    // QKV projections (HMMA bf16x3)
    gemm_hmma<<<dim3(D / BN, MROWS / BM), thr, GEMM_SMEM>>>(x, Wq, qp, MROWS, D, D);
    gemm_hmma<<<dim3((NKV * HD) / BN, MROWS / BM), thr, GEMM_SMEM>>>(x, Wk, kp, MROWS, NKV * HD, D);
    gemm_hmma<<<dim3((NKV * HD) / BN, MROWS / BM), thr, GEMM_SMEM>>>(x, Wv, vp, MROWS, NKV * HD, D);

    // RMSNorm + RoPE
    rmsrope_kernel<<<(262144 + 65536) / 8, thr>>>(rope_cos, rope_sin, q_scale, k_scale);

    // Attention
    attn_kernel<<<NB * NH, thr, ATTN_SMEM_FLOATS * sizeof(float)>>>(qp, kp, vp, op);

    // Output projection
    gemm_hmma<<<dim3(D / BN, MROWS / BM), thr, GEMM_SMEM>>>(op, Wo, out, MROWS, D, D);
}

// round 5
// speedup vs baseline: 2.2750x; 1.4219x over previous
#include <cuda_runtime.h>
#include <cuda_bf16.h>
#include <math.h>

#define NB 64
#define S 256
#define D 1024
#define NH 16
#define NKV 4
#define HD 64
#define NIMG 240
#define MROWS (NB * S)       // 16384
#define KVD (NKV * HD)       // 256

typedef __nv_bfloat16 bf16;

// One big scratch arena (single symbol, host computes offsets)
#define ARENA_BYTES 330000000ULL
__device__ __align__(256) char g_arena[ARENA_BYTES];

// ---------------------------------------------------------------------------
// helpers
// ---------------------------------------------------------------------------
__device__ __forceinline__ unsigned smem_u32(const void* p) {
    unsigned a;
    asm("{ .reg .u64 t; cvta.to.shared.u64 t, %1; cvt.u32.u64 %0, t; }" : "=r"(a) : "l"(p));
    return a;
}
__device__ __forceinline__ void cpa16(unsigned saddr, const void* g) {
    asm volatile("cp.async.cg.shared.global [%0], [%1], 16;" :: "r"(saddr), "l"(g));
}
#define CP_COMMIT() asm volatile("cp.async.commit_group;")
#define CP_WAIT1()  asm volatile("cp.async.wait_group 1;")
#define CP_WAIT0()  asm volatile("cp.async.wait_group 0;")

__device__ __forceinline__ unsigned pack_bf16(bf16 a, bf16 b) {
    return (unsigned)__bfloat16_as_ushort(a) | ((unsigned)__bfloat16_as_ushort(b) << 16);
}
__device__ __forceinline__ void split_bf16(float x, bf16& h, bf16& l) {
    h = __float2bfloat16_rn(x);
    l = __float2bfloat16_rn(x - __bfloat162float(h));
}
__device__ __forceinline__ void mma16816(float c[4], const unsigned a[4],
                                         unsigned b0, unsigned b1) {
    asm volatile(
        "mma.sync.aligned.m16n8k16.row.col.f32.bf16.bf16.f32 "
        "{%0,%1,%2,%3}, {%4,%5,%6,%7}, {%8,%9}, {%0,%1,%2,%3};"
        : "+f"(c[0]), "+f"(c[1]), "+f"(c[2]), "+f"(c[3])
        : "r"(a[0]), "r"(a[1]), "r"(a[2]), "r"(a[3]), "r"(b0), "r"(b1));
}
__device__ __forceinline__ void ldm_x2(unsigned& r0, unsigned& r1, unsigned addr) {
    asm volatile("ldmatrix.sync.aligned.m8n8.x2.shared.b16 {%0,%1}, [%2];"
                 : "=r"(r0), "=r"(r1) : "r"(addr));
}
__device__ __forceinline__ void ldm_x2t(unsigned& r0, unsigned& r1, unsigned addr) {
    asm volatile("ldmatrix.sync.aligned.m8n8.x2.trans.shared.b16 {%0,%1}, [%2];"
                 : "=r"(r0), "=r"(r1) : "r"(addr));
}

// ---------------------------------------------------------------------------
// Prepass: elementwise fp32 -> bf16 hi/lo split (for x)
// ---------------------------------------------------------------------------
__global__ void __launch_bounds__(256)
split_x_kernel(const float* __restrict__ x, bf16* __restrict__ xh,
               bf16* __restrict__ xl, int total4) {
    int i4 = blockIdx.x * 256 + threadIdx.x;
    if (i4 >= total4) return;
    int i = i4 * 4;
    float4 v = *(const float4*)(x + i);
    bf16 h0, l0, h1, l1, h2, l2, h3, l3;
    split_bf16(v.x, h0, l0); split_bf16(v.y, h1, l1);
    split_bf16(v.z, h2, l2); split_bf16(v.w, h3, l3);
    *(uint2*)(xh + i) = make_uint2(pack_bf16(h0, h1), pack_bf16(h2, h3));
    *(uint2*)(xl + i) = make_uint2(pack_bf16(l0, l1), pack_bf16(l2, l3));
}

// ---------------------------------------------------------------------------
// Prepass: weight transpose + split: W[k][n] -> Th[n][k], Tl[n][k]
// ---------------------------------------------------------------------------
__global__ void __launch_bounds__(256)
transp_split_kernel(const float* __restrict__ W, bf16* __restrict__ Th,
                    bf16* __restrict__ Tl, int Kd, int Nd) {
    __shared__ float t[32][33];
    const int n0 = blockIdx.x * 32, k0 = blockIdx.y * 32;
    const int tx = threadIdx.x, ty = threadIdx.y;   // 32 x 8
    #pragma unroll
    for (int i = 0; i < 4; i++)
        t[ty + 8 * i][tx] = W[(size_t)(k0 + ty + 8 * i) * Nd + n0 + tx];
    __syncthreads();
    #pragma unroll
    for (int i = 0; i < 4; i++) {
        float v = t[tx][ty + 8 * i];
        bf16 h, l;
        split_bf16(v, h, l);
        size_t idx = (size_t)(n0 + ty + 8 * i) * Kd + k0 + tx;
        Th[idx] = h;
        Tl[idx] = l;
    }
}

// ---------------------------------------------------------------------------
// HMMA bf16x3 GEMM on pre-split operands.
// A: [M][K] bf16 hi/lo ; B: [N][K] bf16 hi/lo (pre-transposed weights)
// CTA 128x128, BK=32, cp.async double buffer, 8 warps (2x4), warp 64x32.
// mode 0: C fp32.  mode 1: write bf16 hi/lo split to Ch/Cl.
// ---------------------------------------------------------------------------
#define GP 40                       // smem pitch (bf16) per row
#define GTB (128 * GP * 2)          // tile bytes = 10240
#define GEMM_SMEM (2 * 4 * GTB)     // 81920

__global__ void __launch_bounds__(256)
gemm_bf(const bf16* __restrict__ Agh, const bf16* __restrict__ Agl,
        const bf16* __restrict__ Bgh, const bf16* __restrict__ Bgl,
        float* __restrict__ C, bf16* __restrict__ Ch, bf16* __restrict__ Cl,
        int M, int N, int K, int mode) {
    extern __shared__ char smg[];
    const unsigned sb = smem_u32(smg);
    const int tid = threadIdx.x;
    const int wid = tid >> 5;
    const int lane = tid & 31;
    const int lr = lane >> 2, lc = lane & 3;

    const int bm = blockIdx.y * 128;
    const int bn = blockIdx.x * 128;
    const int wm = (wid >> 2) * 64;
    const int wn = (wid & 3) * 32;

    // staging: thread covers 32 bytes (= 16 bf16) of one row per tile,
    // as TWO 16-byte cp.async chunks.
    const int srow = tid >> 1, shalf = tid & 1;
    const size_t gaBase = (size_t)(bm + srow) * K + shalf * 16;   // elements
    const size_t gbBase = (size_t)(bn + srow) * K + shalf * 16;
    const unsigned soff = srow * 80 + shalf * 32;                 // bytes

    float c[4][4][4] = {};
    const int NCH = K / 32;

    // prologue: stage chunk 0 into stage 0
    {
        unsigned base = sb + soff;
        cpa16(base,                Agh + gaBase);
        cpa16(base + 16,           Agh + gaBase + 8);
        cpa16(base + GTB,          Agl + gaBase);
        cpa16(base + GTB + 16,     Agl + gaBase + 8);
        cpa16(base + 2 * GTB,      Bgh + gbBase);
        cpa16(base + 2 * GTB + 16, Bgh + gbBase + 8);
        cpa16(base + 3 * GTB,      Bgl + gbBase);
        cpa16(base + 3 * GTB + 16, Bgl + gbBase + 8);
        CP_COMMIT();
    }

    for (int ch = 0; ch < NCH; ch++) {
        const int s = ch & 1;
        if (ch + 1 < NCH) {
            unsigned base = sb + (s ^ 1) * 4 * GTB + soff;
            size_t ka = gaBase + (size_t)(ch + 1) * 32;
            size_t kb = gbBase + (size_t)(ch + 1) * 32;
            cpa16(base,                Agh + ka);
            cpa16(base + 16,           Agh + ka + 8);
            cpa16(base + GTB,          Agl + ka);
            cpa16(base + GTB + 16,     Agl + ka + 8);
            cpa16(base + 2 * GTB,      Bgh + kb);
            cpa16(base + 2 * GTB + 16, Bgh + kb + 8);
            cpa16(base + 3 * GTB,      Bgl + kb);
            cpa16(base + 3 * GTB + 16, Bgl + kb + 8);
            CP_COMMIT();
            CP_WAIT1();
        } else {
            CP_WAIT0();
        }
        __syncthreads();

        const unsigned* A32h = (const unsigned*)(smg + s * 4 * GTB);
        const unsigned* A32l = (const unsigned*)(smg + s * 4 * GTB + GTB);
        const unsigned* B32h = (const unsigned*)(smg + s * 4 * GTB + 2 * GTB);
        const unsigned* B32l = (const unsigned*)(smg + s * 4 * GTB + 3 * GTB);

        #pragma unroll
        for (int ks = 0; ks < 2; ks++) {
            const int kw = ks * 8 + lc;
            unsigned ah[4][4], al[4][4], bh[4][2], bl[4][2];
            #pragma unroll
            for (int mi = 0; mi < 4; mi++) {
                int r0 = wm + mi * 16 + lr;
                ah[mi][0] = A32h[r0 * 20 + kw];
                ah[mi][1] = A32h[(r0 + 8) * 20 + kw];
                ah[mi][2] = A32h[r0 * 20 + kw + 4];
                ah[mi][3] = A32h[(r0 + 8) * 20 + kw + 4];
                al[mi][0] = A32l[r0 * 20 + kw];
                al[mi][1] = A32l[(r0 + 8) * 20 + kw];
                al[mi][2] = A32l[r0 * 20 + kw + 4];
                al[mi][3] = A32l[(r0 + 8) * 20 + kw + 4];
            }
            #pragma unroll
            for (int ni = 0; ni < 4; ni++) {
                int n0 = wn + ni * 8 + lr;
                bh[ni][0] = B32h[n0 * 20 + kw];
                bh[ni][1] = B32h[n0 * 20 + kw + 4];
                bl[ni][0] = B32l[n0 * 20 + kw];
                bl[ni][1] = B32l[n0 * 20 + kw + 4];
            }
            #pragma unroll
            for (int mi = 0; mi < 4; mi++)
                #pragma unroll
                for (int ni = 0; ni < 4; ni++)
                    mma16816(c[mi][ni], ah[mi], bh[ni][0], bh[ni][1]);
            #pragma unroll
            for (int mi = 0; mi < 4; mi++)
                #pragma unroll
                for (int ni = 0; ni < 4; ni++)
                    mma16816(c[mi][ni], ah[mi], bl[ni][0], bl[ni][1]);
            #pragma unroll
            for (int mi = 0; mi < 4; mi++)
                #pragma unroll
                for (int ni = 0; ni < 4; ni++)
                    mma16816(c[mi][ni], al[mi], bh[ni][0], bh[ni][1]);
        }
        __syncthreads();
    }

    // epilogue
    if (mode == 0) {
        #pragma unroll
        for (int mi = 0; mi < 4; mi++)
            #pragma unroll
            for (int ni = 0; ni < 4; ni++) {
                int r = bm + wm + mi * 16 + lr;
                int col = bn + wn + ni * 8 + lc * 2;
                *(float2*)&C[(size_t)r * N + col] = make_float2(c[mi][ni][0], c[mi][ni][1]);
                *(float2*)&C[(size_t)(r + 8) * N + col] = make_float2(c[mi][ni][2], c[mi][ni][3]);
            }
    } else {
        unsigned* Oh32 = (unsigned*)Ch;
        unsigned* Ol32 = (unsigned*)Cl;
        #pragma unroll
        for (int mi = 0; mi < 4; mi++)
            #pragma unroll
            for (int ni = 0; ni < 4; ni++) {
                int r = bm + wm + mi * 16 + lr;
                int col = bn + wn + ni * 8 + lc * 2;
                bf16 h0, l0, h1, l1;
                split_bf16(c[mi][ni][0], h0, l0);
                split_bf16(c[mi][ni][1], h1, l1);
                Oh32[((size_t)r * N + col) >> 1] = pack_bf16(h0, h1);
                Ol32[((size_t)r * N + col) >> 1] = pack_bf16(l0, l1);
                split_bf16(c[mi][ni][2], h0, l0);
                split_bf16(c[mi][ni][3], h1, l1);
                Oh32[((size_t)(r + 8) * N + col) >> 1] = pack_bf16(h0, h1);
                Ol32[((size_t)(r + 8) * N + col) >> 1] = pack_bf16(l0, l1);
            }
    }
}

// ---------------------------------------------------------------------------
// RMSNorm + RoPE: fp32 Q/K in, bf16 hi/lo out
// ---------------------------------------------------------------------------
__global__ void __launch_bounds__(256)
rmsrope_kernel(const float* __restrict__ Qf, const float* __restrict__ Kf,
               bf16* __restrict__ Qh, bf16* __restrict__ Ql,
               bf16* __restrict__ Kh, bf16* __restrict__ Kl,
               const float* __restrict__ rope_cos, const float* __restrict__ rope_sin,
               const float* __restrict__ q_scale, const float* __restrict__ k_scale) {
    const int w = blockIdx.x * 8 + (threadIdx.x >> 5);
    const int lane = threadIdx.x & 31;

    const float* p;
    bf16 *oh, *ol;
    const float* scale;
    int s_idx;
    size_t base;
    if (w < 262144) {
        int ns = w >> 4;
        int h = w & 15;
        base = (size_t)ns * D + h * HD;
        p = Qf + base; oh = Qh + base; ol = Ql + base;
        scale = q_scale;
        s_idx = ns & 255;
    } else {
        int w2 = w - 262144;
        int ns = w2 >> 2;
        int h = w2 & 3;
        base = (size_t)ns * KVD + h * HD;
        p = Kf + base; oh = Kh + base; ol = Kl + base;
        scale = k_scale;
        s_idx = ns & 255;
    }

    float v1 = p[lane];
    float v2 = p[lane + 32];
    float ss = v1 * v1 + v2 * v2;
    #pragma unroll
    for (int o = 16; o; o >>= 1) ss += __shfl_xor_sync(0xffffffffu, ss, o);
    float r = rsqrtf(ss * (1.0f / 64.0f) + 1e-6f);

    float a = v1 * r * scale[lane];
    float b = v2 * r * scale[lane + 32];
    float cc = rope_cos[s_idx * 32 + lane];
    float sn = rope_sin[s_idx * 32 + lane];
    float r1 = a * cc - b * sn;
    float r2 = b * cc + a * sn;
    bf16 h, l;
    split_bf16(r1, h, l);
    oh[lane] = h; ol[lane] = l;
    split_bf16(r2, h, l);
    oh[lane + 32] = h; ol[lane + 32] = l;
}

// ---------------------------------------------------------------------------
// Flash-attention HMMA kernel.  One CTA per (n,h).  8 warps x 32 q-rows.
// K/V bf16 hi/lo in smem (pitch 72), online softmax over 4 kv-blocks of 64.
// bf16x3 QK^T and PV.  Writes Oh/Ol bf16 split.
// ---------------------------------------------------------------------------
#define KVP 72                                  // smem pitch (bf16)
#define ATTN_SMEM (4 * 256 * KVP * 2)           // 147456 bytes

__global__ void __launch_bounds__(256, 1)
attn_mma(const bf16* __restrict__ Qh, const bf16* __restrict__ Ql,
         const bf16* __restrict__ Kh, const bf16* __restrict__ Kl,
         const bf16* __restrict__ Vh, const bf16* __restrict__ Vl,
         bf16* __restrict__ Oh, bf16* __restrict__ Ol) {
    extern __shared__ char sma[];
    bf16* sKh = (bf16*)sma;
    bf16* sKl = sKh + 256 * KVP;
    bf16* sVh = sKl + 256 * KVP;
    bf16* sVl = sVh + 256 * KVP;

    const int bid = blockIdx.x;
    const int n = bid >> 4;
    const int h = bid & 15;
    const int hkv = h >> 2;
    const int tid = threadIdx.x;
    const int w = tid >> 5;
    const int lane = tid & 31;
    const int lr = lane >> 2, lc = lane & 3;

    // ---- stage K/V hi/lo (coalesced uint4) ----
    {
        const bf16* srcs[4] = {Kh, Kl, Vh, Vl};
        bf16* dsts[4] = {sKh, sKl, sVh, sVl};
        #pragma unroll
        for (int a = 0; a < 4; a++) {
            const char* src = (const char*)(srcs[a] + (size_t)n * 256 * KVD + hkv * HD);
            char* dst = (char*)dsts[a];
            for (int it = tid; it < 2048; it += 256) {
                int row = it >> 3, q = it & 7;
                *(uint4*)(dst + row * (KVP * 2) + q * 16) =
                    *(const uint4*)(src + (size_t)row * (KVD * 2) + q * 16);
            }
        }
    }
    __syncthreads();

    const unsigned uKh = smem_u32(sKh), uKl = smem_u32(sKl);
    const unsigned uVh = smem_u32(sVh), uVl = smem_u32(sVl);
    const unsigned* Q32h = (const unsigned*)Qh;
    const unsigned* Q32l = (const unsigned*)Ql;

    const int wq0 = w * 32;
    float o[2][8][4] = {};
    float mrun[2][2] = {{-3e38f, -3e38f}, {-3e38f, -3e38f}};
    float lrun[2][2] = {{0.f, 0.f}, {0.f, 0.f}};

    for (int j = 0; j < 4; j++) {
        float c[2][8][4] = {};

        // ===== QK^T (bf16x3) =====
        #pragma unroll
        for (int kt = 0; kt < 4; kt++) {
            unsigned qh[2][4], ql[2][4];
            #pragma unroll
            for (int mt = 0; mt < 2; mt++) {
                size_t row = (size_t)n * 256 + wq0 + mt * 16 + lr;
                size_t b0 = row * 512 + h * 32 + kt * 8 + lc;
                qh[mt][0] = Q32h[b0];
                qh[mt][1] = Q32h[b0 + 8 * 512];
                qh[mt][2] = Q32h[b0 + 4];
                qh[mt][3] = Q32h[b0 + 8 * 512 + 4];
                ql[mt][0] = Q32l[b0];
                ql[mt][1] = Q32l[b0 + 8 * 512];
                ql[mt][2] = Q32l[b0 + 4];
                ql[mt][3] = Q32l[b0 + 8 * 512 + 4];
            }
            #pragma unroll
            for (int nt = 0; nt < 8; nt++) {
                int krow = j * 64 + nt * 8 + (lane & 7);
                int kcol = kt * 16 + ((lane >> 3) & 1) * 8;
                unsigned adr = (unsigned)(krow * KVP + kcol) * 2;
                unsigned kh0, kh1, kl0, kl1;
                ldm_x2(kh0, kh1, uKh + adr);
                ldm_x2(kl0, kl1, uKl + adr);
                #pragma unroll
                for (int mt = 0; mt < 2; mt++) {
                    mma16816(c[mt][nt], qh[mt], kh0, kh1);
                    mma16816(c[mt][nt], qh[mt], kl0, kl1);
                    mma16816(c[mt][nt], ql[mt], kh0, kh1);
                }
            }
        }

        // ===== cap + mask + online softmax =====
        #pragma unroll
        for (int mt = 0; mt < 2; mt++) {
            #pragma unroll
            for (int half = 0; half < 2; half++) {
                const int qr = wq0 + mt * 16 + lr + 8 * half;
                float bmax = -3e38f;
                #pragma unroll
                for (int nt = 0; nt < 8; nt++) {
                    #pragma unroll
                    for (int e = 0; e < 2; e++) {
                        float s = c[mt][nt][2 * half + e] * 0.125f;
                        float t = __expf(s * 0.04f);               // 2/50
                        s = 50.0f * __fdividef(t - 1.0f, t + 1.0f);
                        int col = j * 64 + nt * 8 + 2 * lc + e;
                        if (!((qr >= NIMG) || (col < NIMG))) s = -3e38f;
                        c[mt][nt][2 * half + e] = s;
                        bmax = fmaxf(bmax, s);
                    }
                }
                bmax = fmaxf(bmax, __shfl_xor_sync(0xffffffffu, bmax, 1));
                bmax = fmaxf(bmax, __shfl_xor_sync(0xffffffffu, bmax, 2));
                float mold = mrun[mt][half];
                float mnew = fmaxf(mold, bmax);
                float resc = __expf(mold - mnew);
                float rs = 0.0f;
                #pragma unroll
                for (int nt = 0; nt < 8; nt++) {
                    #pragma unroll
                    for (int e = 0; e < 2; e++) {
                        float p = __expf(c[mt][nt][2 * half + e] - mnew);
                        c[mt][nt][2 * half + e] = p;
                        rs += p;
                    }
                }
                rs += __shfl_xor_sync(0xffffffffu, rs, 1);
                rs += __shfl_xor_sync(0xffffffffu, rs, 2);
                lrun[mt][half] = lrun[mt][half] * resc + rs;
                mrun[mt][half] = mnew;
                #pragma unroll
                for (int dt = 0; dt < 8; dt++) {
                    o[mt][dt][2 * half]     *= resc;
                    o[mt][dt][2 * half + 1] *= resc;
                }
            }
        }

        // ===== PV (bf16x3) =====
        #pragma unroll
        for (int kt = 0; kt < 4; kt++) {
            unsigned ph[2][4], pl[2][4];
            #pragma unroll
            for (int mt = 0; mt < 2; mt++) {
                bf16 h0, l0, h1, l1;
                split_bf16(c[mt][2 * kt][0], h0, l0);
                split_bf16(c[mt][2 * kt][1], h1, l1);
                ph[mt][0] = pack_bf16(h0, h1); pl[mt][0] = pack_bf16(l0, l1);
                split_bf16(c[mt][2 * kt][2], h0, l0);
                split_bf16(c[mt][2 * kt][3], h1, l1);
                ph[mt][1] = pack_bf16(h0, h1); pl[mt][1] = pack_bf16(l0, l1);
                split_bf16(c[mt][2 * kt + 1][0], h0, l0);
                split_bf16(c[mt][2 * kt + 1][1], h1, l1);
                ph[mt][2] = pack_bf16(h0, h1); pl[mt][2] = pack_bf16(l0, l1);
                split_bf16(c[mt][2 * kt + 1][2], h0, l0);
                split_bf16(c[mt][2 * kt + 1][3], h1, l1);
                ph[mt][3] = pack_bf16(h0, h1); pl[mt][3] = pack_bf16(l0, l1);
            }
            #pragma unroll
            for (int dt = 0; dt < 8; dt++) {
                int vrow = j * 64 + kt * 16 + (lane & 15);
                unsigned adr = (unsigned)(vrow * KVP + dt * 8) * 2;
                unsigned vh0, vh1, vl0, vl1;
                ldm_x2t(vh0, vh1, uVh + adr);
                ldm_x2t(vl0, vl1, uVl + adr);
                #pragma unroll
                for (int mt = 0; mt < 2; mt++) {
                    mma16816(o[mt][dt], ph[mt], vh0, vh1);
                    mma16816(o[mt][dt], ph[mt], vl0, vl1);
                    mma16816(o[mt][dt], pl[mt], vh0, vh1);
                }
            }
        }
    }

    // ===== epilogue: normalize + split + store =====
    unsigned* O32h = (unsigned*)Oh;
    unsigned* O32l = (unsigned*)Ol;
    #pragma unroll
    for (int mt = 0; mt < 2; mt++) {
        float inv0 = __fdividef(1.0f, lrun[mt][0]);
        float inv1 = __fdividef(1.0f, lrun[mt][1]);
        size_t r0 = (size_t)n * 256 + wq0 + mt * 16 + lr;
        #pragma unroll
        for (int dt = 0; dt < 8; dt++) {
            bf16 h0, l0, h1, l1;
            size_t i0 = r0 * 512 + h * 32 + dt * 4 + lc;
            split_bf16(o[mt][dt][0] * inv0, h0, l0);
            split_bf16(o[mt][dt][1] * inv0, h1, l1);
            O32h[i0] = pack_bf16(h0, h1);
            O32l[i0] = pack_bf16(l0, l1);
            size_t i1 = (r0 + 8) * 512 + h * 32 + dt * 4 + lc;
            split_bf16(o[mt][dt][2] * inv1, h0, l0);
            split_bf16(o[mt][dt][3] * inv1, h1, l1);
            O32h[i1] = pack_bf16(h0, h1);
            O32l[i1] = pack_bf16(l0, l1);
        }
    }
}

// ---------------------------------------------------------------------------
extern "C" void kernel_launch(void* const* d_in, const int* in_sizes, int n_in,
                              void* d_out, int out_size) {
    const float* x        = (const float*)d_in[0];
    const float* rope_cos = (const float*)d_in[2];
    const float* rope_sin = (const float*)d_in[3];
    const float* Wq       = (const float*)d_in[4];
    const float* Wk       = (const float*)d_in[5];
    const float* Wv       = (const float*)d_in[6];
    const float* Wo       = (const float*)d_in[7];
    const float* q_scale  = (const float*)d_in[8];
    const float* k_scale  = (const float*)d_in[9];
    float* out = (float*)d_out;

    char* base;
    cudaGetSymbolAddress((void**)&base, g_arena);
    size_t cur = 0;
    auto alloc = [&](size_t bytes) { char* p = base + cur; cur += (bytes + 255) & ~255ULL; return p; };

    float* Qf = (float*)alloc((size_t)MROWS * D * 4);
    float* Kf = (float*)alloc((size_t)MROWS * KVD * 4);
    bf16* xh  = (bf16*)alloc((size_t)MROWS * D * 2);
    bf16* xl  = (bf16*)alloc((size_t)MROWS * D * 2);
    bf16* Qhh = (bf16*)alloc((size_t)MROWS * D * 2);
    bf16* Qll = (bf16*)alloc((size_t)MROWS * D * 2);
    bf16* Khh = (bf16*)alloc((size_t)MROWS * KVD * 2);
    bf16* Kll = (bf16*)alloc((size_t)MROWS * KVD * 2);
    bf16* Vhh = (bf16*)alloc((size_t)MROWS * KVD * 2);
    bf16* Vll = (bf16*)alloc((size_t)MROWS * KVD * 2);
    bf16* Ohh = (bf16*)alloc((size_t)MROWS * D * 2);
    bf16* Oll = (bf16*)alloc((size_t)MROWS * D * 2);
    bf16* Wqh = (bf16*)alloc((size_t)D * D * 2);
    bf16* Wql = (bf16*)alloc((size_t)D * D * 2);
    bf16* Wkh = (bf16*)alloc((size_t)D * KVD * 2);
    bf16* Wkl = (bf16*)alloc((size_t)D * KVD * 2);
    bf16* Wvh = (bf16*)alloc((size_t)D * KVD * 2);
    bf16* Wvl = (bf16*)alloc((size_t)D * KVD * 2);
    bf16* Woh = (bf16*)alloc((size_t)D * D * 2);
    bf16* Wol = (bf16*)alloc((size_t)D * D * 2);

    cudaFuncSetAttribute(gemm_bf, cudaFuncAttributeMaxDynamicSharedMemorySize, GEMM_SMEM);
    cudaFuncSetAttribute(attn_mma, cudaFuncAttributeMaxDynamicSharedMemorySize, ATTN_SMEM);

    // prepasses
    split_x_kernel<<<MROWS * D / 4 / 256, 256>>>(x, xh, xl, MROWS * D / 4);
    transp_split_kernel<<<dim3(D / 32, D / 32), dim3(32, 8)>>>(Wq, Wqh, Wql, D, D);
    transp_split_kernel<<<dim3(KVD / 32, D / 32), dim3(32, 8)>>>(Wk, Wkh, Wkl, D, KVD);
    transp_split_kernel<<<dim3(KVD / 32, D / 32), dim3(32, 8)>>>(Wv, Wvh, Wvl, D, KVD);
    transp_split_kernel<<<dim3(D / 32, D / 32), dim3(32, 8)>>>(Wo, Woh, Wol, D, D);

    dim3 thr(256);
    // projections
    gemm_bf<<<dim3(D / 128, MROWS / 128), thr, GEMM_SMEM>>>(
        xh, xl, Wqh, Wql, Qf, nullptr, nullptr, MROWS, D, D, 0);
    gemm_bf<<<dim3(KVD / 128, MROWS / 128), thr, GEMM_SMEM>>>(
        xh, xl, Wkh, Wkl, Kf, nullptr, nullptr, MROWS, KVD, D, 0);
    gemm_bf<<<dim3(KVD / 128, MROWS / 128), thr, GEMM_SMEM>>>(
        xh, xl, Wvh, Wvl, nullptr, Vhh, Vll, MROWS, KVD, D, 1);

    // rmsnorm + rope -> bf16 splits
    rmsrope_kernel<<<(262144 + 65536) / 8, thr>>>(
        Qf, Kf, Qhh, Qll, Khh, Kll, rope_cos, rope_sin, q_scale, k_scale);

    // attention
    attn_mma<<<NB * NH, thr, ATTN_SMEM>>>(Qhh, Qll, Khh, Kll, Vhh, Vll, Ohh, Oll);

    // output projection
    gemm_bf<<<dim3(D / 128, MROWS / 128), thr, GEMM_SMEM>>>(
        Ohh, Oll, Woh, Wol, out, nullptr, nullptr, MROWS, D, D, 0);
}

// round 6
// speedup vs baseline: 2.3194x; 1.0195x over previous
#include <cuda_runtime.h>
#include <cuda_bf16.h>
#include <math.h>

#define NB 64
#define S 256
#define D 1024
#define NH 16
#define NKV 4
#define HD 64
#define NIMG 240
#define MROWS (NB * S)       // 16384
#define KVD (NKV * HD)       // 256
#define NFUSE 1536           // packed QKV output columns

typedef __nv_bfloat16 bf16;

#define ARENA_BYTES 330000000ULL
__device__ __align__(256) char g_arena[ARENA_BYTES];

// ---------------------------------------------------------------------------
// helpers
// ---------------------------------------------------------------------------
__device__ __forceinline__ unsigned smem_u32(const void* p) {
    unsigned a;
    asm("{ .reg .u64 t; cvta.to.shared.u64 t, %1; cvt.u32.u64 %0, t; }" : "=r"(a) : "l"(p));
    return a;
}
__device__ __forceinline__ void cpa16(unsigned saddr, const void* g) {
    asm volatile("cp.async.cg.shared.global [%0], [%1], 16;" :: "r"(saddr), "l"(g));
}
#define CP_COMMIT() asm volatile("cp.async.commit_group;")
#define CP_WAIT1()  asm volatile("cp.async.wait_group 1;")
#define CP_WAIT0()  asm volatile("cp.async.wait_group 0;")

__device__ __forceinline__ unsigned pack_bf16(bf16 a, bf16 b) {
    return (unsigned)__bfloat16_as_ushort(a) | ((unsigned)__bfloat16_as_ushort(b) << 16);
}
__device__ __forceinline__ void split_bf16(float x, bf16& h, bf16& l) {
    h = __float2bfloat16_rn(x);
    l = __float2bfloat16_rn(x - __bfloat162float(h));
}
__device__ __forceinline__ void mma16816(float c[4], const unsigned a[4],
                                         unsigned b0, unsigned b1) {
    asm volatile(
        "mma.sync.aligned.m16n8k16.row.col.f32.bf16.bf16.f32 "
        "{%0,%1,%2,%3}, {%4,%5,%6,%7}, {%8,%9}, {%0,%1,%2,%3};"
        : "+f"(c[0]), "+f"(c[1]), "+f"(c[2]), "+f"(c[3])
        : "r"(a[0]), "r"(a[1]), "r"(a[2]), "r"(a[3]), "r"(b0), "r"(b1));
}
__device__ __forceinline__ void ldm_x4(unsigned r[4], unsigned addr) {
    asm volatile("ldmatrix.sync.aligned.m8n8.x4.shared.b16 {%0,%1,%2,%3}, [%4];"
                 : "=r"(r[0]), "=r"(r[1]), "=r"(r[2]), "=r"(r[3]) : "r"(addr));
}
__device__ __forceinline__ void ldm_x2(unsigned& r0, unsigned& r1, unsigned addr) {
    asm volatile("ldmatrix.sync.aligned.m8n8.x2.shared.b16 {%0,%1}, [%2];"
                 : "=r"(r0), "=r"(r1) : "r"(addr));
}
__device__ __forceinline__ void ldm_x2t(unsigned& r0, unsigned& r1, unsigned addr) {
    asm volatile("ldmatrix.sync.aligned.m8n8.x2.trans.shared.b16 {%0,%1}, [%2];"
                 : "=r"(r0), "=r"(r1) : "r"(addr));
}

// ---------------------------------------------------------------------------
// Prepass: elementwise fp32 -> bf16 hi/lo split (for x)
// ---------------------------------------------------------------------------
__global__ void __launch_bounds__(256)
split_x_kernel(const float* __restrict__ x, bf16* __restrict__ xh,
               bf16* __restrict__ xl, int total4) {
    int i4 = blockIdx.x * 256 + threadIdx.x;
    if (i4 >= total4) return;
    int i = i4 * 4;
    float4 v = *(const float4*)(x + i);
    bf16 h0, l0, h1, l1, h2, l2, h3, l3;
    split_bf16(v.x, h0, l0); split_bf16(v.y, h1, l1);
    split_bf16(v.z, h2, l2); split_bf16(v.w, h3, l3);
    *(uint2*)(xh + i) = make_uint2(pack_bf16(h0, h1), pack_bf16(h2, h3));
    *(uint2*)(xl + i) = make_uint2(pack_bf16(l0, l1), pack_bf16(l2, l3));
}

// ---------------------------------------------------------------------------
// Prepass: weight transpose + split into packed [rowOff + n][k] buffer
// ---------------------------------------------------------------------------
__global__ void __launch_bounds__(256)
transp_split_kernel(const float* __restrict__ W, bf16* __restrict__ Th,
                    bf16* __restrict__ Tl, int Kd, int Nd, int rowOff) {
    __shared__ float t[32][33];
    const int n0 = blockIdx.x * 32, k0 = blockIdx.y * 32;
    const int tx = threadIdx.x, ty = threadIdx.y;   // 32 x 8
    #pragma unroll
    for (int i = 0; i < 4; i++)
        t[ty + 8 * i][tx] = W[(size_t)(k0 + ty + 8 * i) * Nd + n0 + tx];
    __syncthreads();
    #pragma unroll
    for (int i = 0; i < 4; i++) {
        float v = t[tx][ty + 8 * i];
        bf16 h, l;
        split_bf16(v, h, l);
        size_t idx = (size_t)(rowOff + n0 + ty + 8 * i) * Kd + k0 + tx;
        Th[idx] = h;
        Tl[idx] = l;
    }
}

// ---------------------------------------------------------------------------
// HMMA bf16x3 GEMM, ldmatrix fragment loads.
// A: [M][K] bf16 hi/lo ; B: [N][K] bf16 hi/lo.
// CTA 128x128, BK=32, cp.async double buffer, 8 warps (2x4), warp 64x32.
// mode 0: C fp32 at stride N.
// mode 2: fused QKV routing (cols<1024 -> Qf fp32; <1280 -> Kf fp32;
//         else -> Vh/Vl bf16 split).
// ---------------------------------------------------------------------------
#define GP 40                       // smem pitch (bf16) per row
#define GTB (128 * GP * 2)          // tile bytes = 10240
#define GEMM_SMEM (2 * 4 * GTB)     // 81920

__global__ void __launch_bounds__(256)
gemm_bf(const bf16* __restrict__ Agh, const bf16* __restrict__ Agl,
        const bf16* __restrict__ Bgh, const bf16* __restrict__ Bgl,
        float* __restrict__ C, float* __restrict__ C2,
        bf16* __restrict__ Ch, bf16* __restrict__ Cl,
        int M, int N, int K, int mode) {
    extern __shared__ char smg[];
    const unsigned sb = smem_u32(smg);
    const int tid = threadIdx.x;
    const int wid = tid >> 5;
    const int lane = tid & 31;
    const int lr = lane >> 2, lc = lane & 3;

    const int bm = blockIdx.y * 128;
    const int bn = blockIdx.x * 128;
    const int wm = (wid >> 2) * 64;
    const int wn = (wid & 3) * 32;

    // cp.async staging: thread covers 32B of one row, two 16B chunks
    const int srow = tid >> 1, shalf = tid & 1;
    const size_t gaBase = (size_t)(bm + srow) * K + shalf * 16;
    const size_t gbBase = (size_t)(bn + srow) * K + shalf * 16;
    const unsigned soff = srow * 80 + shalf * 32;

    // ldmatrix per-lane bases (bytes within a tile)
    const unsigned aBase = (unsigned)((wm + (lane & 7) + ((lane >> 3) & 1) * 8) * 80
                                      + ((lane >> 4) & 1) * 16);
    const unsigned bBase = (unsigned)((wn + (lane & 7)) * 80 + ((lane >> 3) & 1) * 16);

    float c[4][4][4] = {};
    const int NCH = K / 32;

    // prologue: stage chunk 0 into stage 0
    {
        unsigned base = sb + soff;
        cpa16(base,                Agh + gaBase);
        cpa16(base + 16,           Agh + gaBase + 8);
        cpa16(base + GTB,          Agl + gaBase);
        cpa16(base + GTB + 16,     Agl + gaBase + 8);
        cpa16(base + 2 * GTB,      Bgh + gbBase);
        cpa16(base + 2 * GTB + 16, Bgh + gbBase + 8);
        cpa16(base + 3 * GTB,      Bgl + gbBase);
        cpa16(base + 3 * GTB + 16, Bgl + gbBase + 8);
        CP_COMMIT();
    }

    for (int ch = 0; ch < NCH; ch++) {
        const int s = ch & 1;
        if (ch + 1 < NCH) {
            unsigned base = sb + (s ^ 1) * 4 * GTB + soff;
            size_t ka = gaBase + (size_t)(ch + 1) * 32;
            size_t kb = gbBase + (size_t)(ch + 1) * 32;
            cpa16(base,                Agh + ka);
            cpa16(base + 16,           Agh + ka + 8);
            cpa16(base + GTB,          Agl + ka);
            cpa16(base + GTB + 16,     Agl + ka + 8);
            cpa16(base + 2 * GTB,      Bgh + kb);
            cpa16(base + 2 * GTB + 16, Bgh + kb + 8);
            cpa16(base + 3 * GTB,      Bgl + kb);
            cpa16(base + 3 * GTB + 16, Bgl + kb + 8);
            CP_COMMIT();
            CP_WAIT1();
        } else {
            CP_WAIT0();
        }
        __syncthreads();

        const unsigned uAh = sb + s * 4 * GTB;
        const unsigned uAl = uAh + GTB;
        const unsigned uBh = uAh + 2 * GTB;
        const unsigned uBl = uAh + 3 * GTB;

        #pragma unroll
        for (int ks = 0; ks < 2; ks++) {
            const unsigned ko = ks * 32;   // 16 elems = 32 bytes
            unsigned ah[4][4], al[4][4], bh[4][2], bl[4][2];
            #pragma unroll
            for (int mi = 0; mi < 4; mi++) {
                unsigned adr = aBase + mi * 16 * 80 + ko;
                ldm_x4(ah[mi], uAh + adr);
                ldm_x4(al[mi], uAl + adr);
            }
            #pragma unroll
            for (int ni = 0; ni < 4; ni++) {
                unsigned adr = bBase + ni * 8 * 80 + ko;
                ldm_x2(bh[ni][0], bh[ni][1], uBh + adr);
                ldm_x2(bl[ni][0], bl[ni][1], uBl + adr);
            }
            #pragma unroll
            for (int mi = 0; mi < 4; mi++)
                #pragma unroll
                for (int ni = 0; ni < 4; ni++)
                    mma16816(c[mi][ni], ah[mi], bh[ni][0], bh[ni][1]);
            #pragma unroll
            for (int mi = 0; mi < 4; mi++)
                #pragma unroll
                for (int ni = 0; ni < 4; ni++)
                    mma16816(c[mi][ni], ah[mi], bl[ni][0], bl[ni][1]);
            #pragma unroll
            for (int mi = 0; mi < 4; mi++)
                #pragma unroll
                for (int ni = 0; ni < 4; ni++)
                    mma16816(c[mi][ni], al[mi], bh[ni][0], bh[ni][1]);
        }
        __syncthreads();
    }

    // ---- epilogue ----
    if (mode == 0) {
        #pragma unroll
        for (int mi = 0; mi < 4; mi++)
            #pragma unroll
            for (int ni = 0; ni < 4; ni++) {
                int r = bm + wm + mi * 16 + lr;
                int col = bn + wn + ni * 8 + lc * 2;
                *(float2*)&C[(size_t)r * N + col] = make_float2(c[mi][ni][0], c[mi][ni][1]);
                *(float2*)&C[(size_t)(r + 8) * N + col] = make_float2(c[mi][ni][2], c[mi][ni][3]);
            }
    } else {
        // fused QKV routing: bn is uniform per CTA
        if (bn < 1024) {
            #pragma unroll
            for (int mi = 0; mi < 4; mi++)
                #pragma unroll
                for (int ni = 0; ni < 4; ni++) {
                    int r = bm + wm + mi * 16 + lr;
                    int col = bn + wn + ni * 8 + lc * 2;
                    *(float2*)&C[(size_t)r * D + col] = make_float2(c[mi][ni][0], c[mi][ni][1]);
                    *(float2*)&C[(size_t)(r + 8) * D + col] = make_float2(c[mi][ni][2], c[mi][ni][3]);
                }
        } else if (bn < 1280) {
            #pragma unroll
            for (int mi = 0; mi < 4; mi++)
                #pragma unroll
                for (int ni = 0; ni < 4; ni++) {
                    int r = bm + wm + mi * 16 + lr;
                    int col = (bn - 1024) + wn + ni * 8 + lc * 2;
                    *(float2*)&C2[(size_t)r * KVD + col] = make_float2(c[mi][ni][0], c[mi][ni][1]);
                    *(float2*)&C2[(size_t)(r + 8) * KVD + col] = make_float2(c[mi][ni][2], c[mi][ni][3]);
                }
        } else {
            unsigned* Oh32 = (unsigned*)Ch;
            unsigned* Ol32 = (unsigned*)Cl;
            #pragma unroll
            for (int mi = 0; mi < 4; mi++)
                #pragma unroll
                for (int ni = 0; ni < 4; ni++) {
                    int r = bm + wm + mi * 16 + lr;
                    int col = (bn - 1280) + wn + ni * 8 + lc * 2;
                    bf16 h0, l0, h1, l1;
                    split_bf16(c[mi][ni][0], h0, l0);
                    split_bf16(c[mi][ni][1], h1, l1);
                    Oh32[((size_t)r * KVD + col) >> 1] = pack_bf16(h0, h1);
                    Ol32[((size_t)r * KVD + col) >> 1] = pack_bf16(l0, l1);
                    split_bf16(c[mi][ni][2], h0, l0);
                    split_bf16(c[mi][ni][3], h1, l1);
                    Oh32[((size_t)(r + 8) * KVD + col) >> 1] = pack_bf16(h0, h1);
                    Ol32[((size_t)(r + 8) * KVD + col) >> 1] = pack_bf16(l0, l1);
                }
        }
    }
}

// ---------------------------------------------------------------------------
// RMSNorm + RoPE: fp32 Q/K in, bf16 hi/lo out
// ---------------------------------------------------------------------------
__global__ void __launch_bounds__(256)
rmsrope_kernel(const float* __restrict__ Qf, const float* __restrict__ Kf,
               bf16* __restrict__ Qh, bf16* __restrict__ Ql,
               bf16* __restrict__ Kh, bf16* __restrict__ Kl,
               const float* __restrict__ rope_cos, const float* __restrict__ rope_sin,
               const float* __restrict__ q_scale, const float* __restrict__ k_scale) {
    const int w = blockIdx.x * 8 + (threadIdx.x >> 5);
    const int lane = threadIdx.x & 31;

    const float* p;
    bf16 *oh, *ol;
    const float* scale;
    int s_idx;
    size_t base;
    if (w < 262144) {
        int ns = w >> 4;
        int h = w & 15;
        base = (size_t)ns * D + h * HD;
        p = Qf + base; oh = Qh + base; ol = Ql + base;
        scale = q_scale;
        s_idx = ns & 255;
    } else {
        int w2 = w - 262144;
        int ns = w2 >> 2;
        int h = w2 & 3;
        base = (size_t)ns * KVD + h * HD;
        p = Kf + base; oh = Kh + base; ol = Kl + base;
        scale = k_scale;
        s_idx = ns & 255;
    }

    float v1 = p[lane];
    float v2 = p[lane + 32];
    float ss = v1 * v1 + v2 * v2;
    #pragma unroll
    for (int o = 16; o; o >>= 1) ss += __shfl_xor_sync(0xffffffffu, ss, o);
    float r = rsqrtf(ss * (1.0f / 64.0f) + 1e-6f);

    float a = v1 * r * scale[lane];
    float b = v2 * r * scale[lane + 32];
    float cc = rope_cos[s_idx * 32 + lane];
    float sn = rope_sin[s_idx * 32 + lane];
    float r1 = a * cc - b * sn;
    float r2 = b * cc + a * sn;
    bf16 h, l;
    split_bf16(r1, h, l);
    oh[lane] = h; ol[lane] = l;
    split_bf16(r2, h, l);
    oh[lane + 32] = h; ol[lane + 32] = l;
}

// ---------------------------------------------------------------------------
// Flash-attention HMMA kernel (unchanged from R5 pass).
// ---------------------------------------------------------------------------
#define KVP 72
#define ATTN_SMEM (4 * 256 * KVP * 2)

__global__ void __launch_bounds__(256, 1)
attn_mma(const bf16* __restrict__ Qh, const bf16* __restrict__ Ql,
         const bf16* __restrict__ Kh, const bf16* __restrict__ Kl,
         const bf16* __restrict__ Vh, const bf16* __restrict__ Vl,
         bf16* __restrict__ Oh, bf16* __restrict__ Ol) {
    extern __shared__ char sma[];
    bf16* sKh = (bf16*)sma;
    bf16* sKl = sKh + 256 * KVP;
    bf16* sVh = sKl + 256 * KVP;
    bf16* sVl = sVh + 256 * KVP;

    const int bid = blockIdx.x;
    const int n = bid >> 4;
    const int h = bid & 15;
    const int hkv = h >> 2;
    const int tid = threadIdx.x;
    const int w = tid >> 5;
    const int lane = tid & 31;
    const int lr = lane >> 2, lc = lane & 3;

    {
        const bf16* srcs[4] = {Kh, Kl, Vh, Vl};
        bf16* dsts[4] = {sKh, sKl, sVh, sVl};
        #pragma unroll
        for (int a = 0; a < 4; a++) {
            const char* src = (const char*)(srcs[a] + (size_t)n * 256 * KVD + hkv * HD);
            char* dst = (char*)dsts[a];
            for (int it = tid; it < 2048; it += 256) {
                int row = it >> 3, q = it & 7;
                *(uint4*)(dst + row * (KVP * 2) + q * 16) =
                    *(const uint4*)(src + (size_t)row * (KVD * 2) + q * 16);
            }
        }
    }
    __syncthreads();

    const unsigned uKh = smem_u32(sKh), uKl = smem_u32(sKl);
    const unsigned uVh = smem_u32(sVh), uVl = smem_u32(sVl);
    const unsigned* Q32h = (const unsigned*)Qh;
    const unsigned* Q32l = (const unsigned*)Ql;

    const int wq0 = w * 32;
    float o[2][8][4] = {};
    float mrun[2][2] = {{-3e38f, -3e38f}, {-3e38f, -3e38f}};
    float lrun[2][2] = {{0.f, 0.f}, {0.f, 0.f}};

    for (int j = 0; j < 4; j++) {
        float c[2][8][4] = {};

        #pragma unroll
        for (int kt = 0; kt < 4; kt++) {
            unsigned qh[2][4], ql[2][4];
            #pragma unroll
            for (int mt = 0; mt < 2; mt++) {
                size_t row = (size_t)n * 256 + wq0 + mt * 16 + lr;
                size_t b0 = row * 512 + h * 32 + kt * 8 + lc;
                qh[mt][0] = Q32h[b0];
                qh[mt][1] = Q32h[b0 + 8 * 512];
                qh[mt][2] = Q32h[b0 + 4];
                qh[mt][3] = Q32h[b0 + 8 * 512 + 4];
                ql[mt][0] = Q32l[b0];
                ql[mt][1] = Q32l[b0 + 8 * 512];
                ql[mt][2] = Q32l[b0 + 4];
                ql[mt][3] = Q32l[b0 + 8 * 512 + 4];
            }
            #pragma unroll
            for (int nt = 0; nt < 8; nt++) {
                int krow = j * 64 + nt * 8 + (lane & 7);
                int kcol = kt * 16 + ((lane >> 3) & 1) * 8;
                unsigned adr = (unsigned)(krow * KVP + kcol) * 2;
                unsigned kh0, kh1, kl0, kl1;
                ldm_x2(kh0, kh1, uKh + adr);
                ldm_x2(kl0, kl1, uKl + adr);
                #pragma unroll
                for (int mt = 0; mt < 2; mt++) {
                    mma16816(c[mt][nt], qh[mt], kh0, kh1);
                    mma16816(c[mt][nt], qh[mt], kl0, kl1);
                    mma16816(c[mt][nt], ql[mt], kh0, kh1);
                }
            }
        }

        #pragma unroll
        for (int mt = 0; mt < 2; mt++) {
            #pragma unroll
            for (int half = 0; half < 2; half++) {
                const int qr = wq0 + mt * 16 + lr + 8 * half;
                float bmax = -3e38f;
                #pragma unroll
                for (int nt = 0; nt < 8; nt++) {
                    #pragma unroll
                    for (int e = 0; e < 2; e++) {
                        float s = c[mt][nt][2 * half + e] * 0.125f;
                        float t = __expf(s * 0.04f);
                        s = 50.0f * __fdividef(t - 1.0f, t + 1.0f);
                        int col = j * 64 + nt * 8 + 2 * lc + e;
                        if (!((qr >= NIMG) || (col < NIMG))) s = -3e38f;
                        c[mt][nt][2 * half + e] = s;
                        bmax = fmaxf(bmax, s);
                    }
                }
                bmax = fmaxf(bmax, __shfl_xor_sync(0xffffffffu, bmax, 1));
                bmax = fmaxf(bmax, __shfl_xor_sync(0xffffffffu, bmax, 2));
                float mold = mrun[mt][half];
                float mnew = fmaxf(mold, bmax);
                float resc = __expf(mold - mnew);
                float rs = 0.0f;
                #pragma unroll
                for (int nt = 0; nt < 8; nt++) {
                    #pragma unroll
                    for (int e = 0; e < 2; e++) {
                        float p = __expf(c[mt][nt][2 * half + e] - mnew);
                        c[mt][nt][2 * half + e] = p;
                        rs += p;
                    }
                }
                rs += __shfl_xor_sync(0xffffffffu, rs, 1);
                rs += __shfl_xor_sync(0xffffffffu, rs, 2);
                lrun[mt][half] = lrun[mt][half] * resc + rs;
                mrun[mt][half] = mnew;
                #pragma unroll
                for (int dt = 0; dt < 8; dt++) {
                    o[mt][dt][2 * half]     *= resc;
                    o[mt][dt][2 * half + 1] *= resc;
                }
            }
        }

        #pragma unroll
        for (int kt = 0; kt < 4; kt++) {
            unsigned ph[2][4], pl[2][4];
            #pragma unroll
            for (int mt = 0; mt < 2; mt++) {
                bf16 h0, l0, h1, l1;
                split_bf16(c[mt][2 * kt][0], h0, l0);
                split_bf16(c[mt][2 * kt][1], h1, l1);
                ph[mt][0] = pack_bf16(h0, h1); pl[mt][0] = pack_bf16(l0, l1);
                split_bf16(c[mt][2 * kt][2], h0, l0);
                split_bf16(c[mt][2 * kt][3], h1, l1);
                ph[mt][1] = pack_bf16(h0, h1); pl[mt][1] = pack_bf16(l0, l1);
                split_bf16(c[mt][2 * kt + 1][0], h0, l0);
                split_bf16(c[mt][2 * kt + 1][1], h1, l1);
                ph[mt][2] = pack_bf16(h0, h1); pl[mt][2] = pack_bf16(l0, l1);
                split_bf16(c[mt][2 * kt + 1][2], h0, l0);
                split_bf16(c[mt][2 * kt + 1][3], h1, l1);
                ph[mt][3] = pack_bf16(h0, h1); pl[mt][3] = pack_bf16(l0, l1);
            }
            #pragma unroll
            for (int dt = 0; dt < 8; dt++) {
                int vrow = j * 64 + kt * 16 + (lane & 15);
                unsigned adr = (unsigned)(vrow * KVP + dt * 8) * 2;
                unsigned vh0, vh1, vl0, vl1;
                ldm_x2t(vh0, vh1, uVh + adr);
                ldm_x2t(vl0, vl1, uVl + adr);
                #pragma unroll
                for (int mt = 0; mt < 2; mt++) {
                    mma16816(o[mt][dt], ph[mt], vh0, vh1);
                    mma16816(o[mt][dt], ph[mt], vl0, vl1);
                    mma16816(o[mt][dt], pl[mt], vh0, vh1);
                }
            }
        }
    }

    unsigned* O32h = (unsigned*)Oh;
    unsigned* O32l = (unsigned*)Ol;
    #pragma unroll
    for (int mt = 0; mt < 2; mt++) {
        float inv0 = __fdividef(1.0f, lrun[mt][0]);
        float inv1 = __fdividef(1.0f, lrun[mt][1]);
        size_t r0 = (size_t)n * 256 + wq0 + mt * 16 + lr;
        #pragma unroll
        for (int dt = 0; dt < 8; dt++) {
            bf16 h0, l0, h1, l1;
            size_t i0 = r0 * 512 + h * 32 + dt * 4 + lc;
            split_bf16(o[mt][dt][0] * inv0, h0, l0);
            split_bf16(o[mt][dt][1] * inv0, h1, l1);
            O32h[i0] = pack_bf16(h0, h1);
            O32l[i0] = pack_bf16(l0, l1);
            size_t i1 = (r0 + 8) * 512 + h * 32 + dt * 4 + lc;
            split_bf16(o[mt][dt][2] * inv1, h0, l0);
            split_bf16(o[mt][dt][3] * inv1, h1, l1);
            O32h[i1] = pack_bf16(h0, h1);
            O32l[i1] = pack_bf16(l0, l1);
        }
    }
}

// ---------------------------------------------------------------------------
extern "C" void kernel_launch(void* const* d_in, const int* in_sizes, int n_in,
                              void* d_out, int out_size) {
    const float* x        = (const float*)d_in[0];
    const float* rope_cos = (const float*)d_in[2];
    const float* rope_sin = (const float*)d_in[3];
    const float* Wq       = (const float*)d_in[4];
    const float* Wk       = (const float*)d_in[5];
    const float* Wv       = (const float*)d_in[6];
    const float* Wo       = (const float*)d_in[7];
    const float* q_scale  = (const float*)d_in[8];
    const float* k_scale  = (const float*)d_in[9];
    float* out = (float*)d_out;

    char* base;
    cudaGetSymbolAddress((void**)&base, g_arena);
    size_t cur = 0;
    auto alloc = [&](size_t bytes) { char* p = base + cur; cur += (bytes + 255) & ~255ULL; return p; };

    float* Qf = (float*)alloc((size_t)MROWS * D * 4);
    float* Kf = (float*)alloc((size_t)MROWS * KVD * 4);
    bf16* xh  = (bf16*)alloc((size_t)MROWS * D * 2);
    bf16* xl  = (bf16*)alloc((size_t)MROWS * D * 2);
    bf16* Qhh = (bf16*)alloc((size_t)MROWS * D * 2);
    bf16* Qll = (bf16*)alloc((size_t)MROWS * D * 2);
    bf16* Khh = (bf16*)alloc((size_t)MROWS * KVD * 2);
    bf16* Kll = (bf16*)alloc((size_t)MROWS * KVD * 2);
    bf16* Vhh = (bf16*)alloc((size_t)MROWS * KVD * 2);
    bf16* Vll = (bf16*)alloc((size_t)MROWS * KVD * 2);
    bf16* Ohh = (bf16*)alloc((size_t)MROWS * D * 2);
    bf16* Oll = (bf16*)alloc((size_t)MROWS * D * 2);
    bf16* Wph = (bf16*)alloc((size_t)NFUSE * D * 2);   // packed QKV weights^T
    bf16* Wpl = (bf16*)alloc((size_t)NFUSE * D * 2);
    bf16* Woh = (bf16*)alloc((size_t)D * D * 2);
    bf16* Wol = (bf16*)alloc((size_t)D * D * 2);

    cudaFuncSetAttribute(gemm_bf, cudaFuncAttributeMaxDynamicSharedMemorySize, GEMM_SMEM);
    cudaFuncSetAttribute(attn_mma, cudaFuncAttributeMaxDynamicSharedMemorySize, ATTN_SMEM);

    // prepasses
    split_x_kernel<<<MROWS * D / 4 / 256, 256>>>(x, xh, xl, MROWS * D / 4);
    transp_split_kernel<<<dim3(D / 32, D / 32), dim3(32, 8)>>>(Wq, Wph, Wpl, D, D, 0);
    transp_split_kernel<<<dim3(KVD / 32, D / 32), dim3(32, 8)>>>(Wk, Wph, Wpl, D, KVD, 1024);
    transp_split_kernel<<<dim3(KVD / 32, D / 32), dim3(32, 8)>>>(Wv, Wph, Wpl, D, KVD, 1280);
    transp_split_kernel<<<dim3(D / 32, D / 32), dim3(32, 8)>>>(Wo, Woh, Wol, D, D, 0);

    dim3 thr(256);
    // fused QKV projection (N = 1536)
    gemm_bf<<<dim3(NFUSE / 128, MROWS / 128), thr, GEMM_SMEM>>>(
        xh, xl, Wph, Wpl, Qf, Kf, Vhh, Vll, MROWS, NFUSE, D, 2);

    // rmsnorm + rope -> bf16 splits
    rmsrope_kernel<<<(262144 + 65536) / 8, thr>>>(
        Qf, Kf, Qhh, Qll, Khh, Kll, rope_cos, rope_sin, q_scale, k_scale);

    // attention
    attn_mma<<<NB * NH, thr, ATTN_SMEM>>>(Qhh, Qll, Khh, Kll, Vhh, Vll, Ohh, Oll);

    // output projection
    gemm_bf<<<dim3(D / 128, MROWS / 128), thr, GEMM_SMEM>>>(
        Ohh, Oll, Woh, Wol, out, nullptr, nullptr, nullptr, MROWS, D, D, 0);
}